// round 12
// baseline (speedup 1.0000x reference)
#include <cuda_runtime.h>
#include <cstdint>

// VecArrayMultiplier54x54 — converged champion (R12 == R9 configuration).
//
// Insight: the reference's differentiable {0,1} gate network (XOR/AND/OR +
// 53 chained 108-bit ripple-carry adds) is EXACT on {0,1} inputs, so
// out[row] = bits of (uint54(A[row]) * uint54(B[row])), LSB first, as 0/1 floats.
//
// Measured landscape (warm e2e, GB300): warps 1024->8.93us, 2048->6.624us (opt),
// 2432->6.66, 4096->6.88, 8192->6.88; instruction count, L2-line locality and
// wave balance all non-binding — the floor is launch/ramp overhead.
//
// Shape: 256 CTAs x 256 threads = 2048 warps, 4 rows/warp strided by NWARPS
// (row offsets i*NWARPS*54 are compile-time constants -> LDG immediate form),
// guard-free for batch = 8192:
//   - 16 independent front-batched LDG.32 per thread-slot (one exposed
//     memory round trip per warp)
//   - 4 ballots/row -> two 54-bit operands -> 64x64->128 IMAD multiply
//   - lane<27 builds 4 floats as bit patterns (bit * 0x3F800000, no I2F)
//     and writes one STG.128 per row
// regs=27, cold dur 4.992us, warm e2e 6.624us, rel_err 0.

#define ROWS_PER_WARP 4

template<int NWARPS>
__global__ void __launch_bounds__(256)
mul54x54_final_kernel(const float* __restrict__ A,
                      const float* __restrict__ B,
                      float* __restrict__ out) {
    const int gwarp = (int)((blockIdx.x * blockDim.x + threadIdx.x) >> 5);
    const int lane  = threadIdx.x & 31;

    const float* __restrict__ a0 = A + (size_t)gwarp * 54;
    const float* __restrict__ b0 = B + (size_t)gwarp * 54;

    float av0[ROWS_PER_WARP], bv0[ROWS_PER_WARP];
    float av1[ROWS_PER_WARP], bv1[ROWS_PER_WARP];

    const bool tail = (lane < 22);

    // 16 independent LDG.32, constant offsets i*NWARPS*54 from one base.
    #pragma unroll
    for (int i = 0; i < ROWS_PER_WARP; i++) {
        const size_t off = (size_t)i * NWARPS * 54;
        av0[i] = a0[off + lane];
        bv0[i] = b0[off + lane];
        av1[i] = 0.0f; bv1[i] = 0.0f;
        if (tail) {
            av1[i] = a0[off + 32 + lane];
            bv1[i] = b0[off + 32 + lane];
        }
    }

    #pragma unroll
    for (int i = 0; i < ROWS_PER_WARP; i++) {
        unsigned ma0 = __ballot_sync(0xFFFFFFFFu, av0[i] > 0.5f);
        unsigned ma1 = __ballot_sync(0xFFFFFFFFu, av1[i] > 0.5f);
        unsigned mb0 = __ballot_sync(0xFFFFFFFFu, bv0[i] > 0.5f);
        unsigned mb1 = __ballot_sync(0xFFFFFFFFu, bv1[i] > 0.5f);

        const uint64_t a = (uint64_t)ma0 | ((uint64_t)(ma1 & 0x3FFFFFu) << 32);
        const uint64_t b = (uint64_t)mb0 | ((uint64_t)(mb1 & 0x3FFFFFu) << 32);

        const uint64_t lo = a * b;             // product bits [0:64)
        const uint64_t hi = __umul64hi(a, b);  // product bits [64:108)

        if (lane < 27) {
            unsigned nib = (lane < 16) ? (unsigned)(lo >> (lane * 4))
                                       : (unsigned)(hi >> ((lane - 16) * 4));
            uint4 v;
            v.x = ( nib        & 1u) * 0x3F800000u;
            v.y = ((nib >> 1)  & 1u) * 0x3F800000u;
            v.z = ((nib >> 2)  & 1u) * 0x3F800000u;
            v.w = ((nib >> 3)  & 1u) * 0x3F800000u;
            ((uint4*)(out + ((size_t)gwarp + (size_t)i * NWARPS) * 108))[lane] = v;
        }
    }
}

// Generic fallback for unexpected batch sizes (1 row/warp, guarded).
__global__ void __launch_bounds__(256)
mul54x54_generic_kernel(const float* __restrict__ A,
                        const float* __restrict__ B,
                        float* __restrict__ out,
                        int batch) {
    const int row  = (int)((blockIdx.x * blockDim.x + threadIdx.x) >> 5);
    const int lane = threadIdx.x & 31;
    if (row >= batch) return;

    const float* __restrict__ a_row = A + (size_t)row * 54;
    const float* __restrict__ b_row = B + (size_t)row * 54;

    float av0 = a_row[lane], bv0 = b_row[lane];
    float av1 = 0.0f, bv1 = 0.0f;
    if (lane < 22) { av1 = a_row[32 + lane]; bv1 = b_row[32 + lane]; }

    unsigned ma0 = __ballot_sync(0xFFFFFFFFu, av0 > 0.5f);
    unsigned ma1 = __ballot_sync(0xFFFFFFFFu, av1 > 0.5f);
    unsigned mb0 = __ballot_sync(0xFFFFFFFFu, bv0 > 0.5f);
    unsigned mb1 = __ballot_sync(0xFFFFFFFFu, bv1 > 0.5f);

    const uint64_t a = (uint64_t)ma0 | ((uint64_t)(ma1 & 0x3FFFFFu) << 32);
    const uint64_t b = (uint64_t)mb0 | ((uint64_t)(mb1 & 0x3FFFFFu) << 32);
    const uint64_t lo = a * b;
    const uint64_t hi = __umul64hi(a, b);

    if (lane < 27) {
        unsigned nib = (lane < 16) ? (unsigned)(lo >> (lane * 4))
                                   : (unsigned)(hi >> ((lane - 16) * 4));
        uint4 v;
        v.x = ( nib        & 1u) * 0x3F800000u;
        v.y = ((nib >> 1)  & 1u) * 0x3F800000u;
        v.z = ((nib >> 2)  & 1u) * 0x3F800000u;
        v.w = ((nib >> 3)  & 1u) * 0x3F800000u;
        ((uint4*)(out + (size_t)row * 108))[lane] = v;
    }
}

extern "C" void kernel_launch(void* const* d_in, const int* in_sizes, int n_in,
                              void* d_out, int out_size) {
    const float* A = (const float*)d_in[0];
    const float* B = (const float*)d_in[1];
    float* out = (float*)d_out;

    const int batch = in_sizes[0] / 54;     // 8192 expected
    constexpr int NWARPS = 2048;            // 256 CTAs x 256 threads

    if (batch == NWARPS * ROWS_PER_WARP) {
        mul54x54_final_kernel<NWARPS><<<256, 256>>>(A, B, out);
    } else {
        const int blocks = (batch + 7) / 8; // 1 row/warp fallback
        mul54x54_generic_kernel<<<blocks, 256>>>(A, B, out, batch);
    }
}

// round 13
// speedup vs baseline: 1.1082x; 1.1082x over previous
#include <cuda_runtime.h>
#include <cstdint>

// VecArrayMultiplier54x54 — converged final kernel (R13 == R11 configuration).
//
// Insight: the reference's differentiable {0,1} gate network (XOR/AND/OR
// gates + 53 chained 108-bit ripple-carry adders) is EXACT on {0,1} inputs,
// so out[row] = bits of (uint54(A[row]) * uint54(B[row])), LSB first, 0/1 floats.
//
// Session findings (GB300, warm graph-replay e2e):
//   - warps: 1024 -> 8.93us (starved), 2048..8192 -> 6.62-6.93us plateau
//   - run-to-run noise +-0.25us (identical binary: 6.624 vs 6.880)
//   - instruction count (-20%), LDG width, L2-line locality, wave balance,
//     CTA geometry: all individually falsified as binding
//   => floor = per-replay launch/ramp overhead + ~1us warm kernel (L2-resident).
//
// Shape: 128 CTAs x 512 threads = 2048 warps, 4 rows/warp BLOCKED
// (warp w -> rows 4w..4w+3; contiguous 864B input / 1728B output spans,
// constant immediate load offsets), guard-free for batch = 8192:
//   - 16 independent front-batched LDG.32 per thread-slot
//   - 4 ballots/row -> 54-bit operands -> 64x64->128 IMAD multiply
//   - lane<27: 4 floats built as bit patterns (bit * 0x3F800000, no I2F),
//     one STG.128 per row
// regs=27, cold ncu dur 4.99us, warm e2e 6.62-6.88us, rel_err 0.

#define ROWS_PER_WARP 4

__global__ void __launch_bounds__(512)
mul54x54_final_kernel(const float* __restrict__ A,
                      const float* __restrict__ B,
                      float* __restrict__ out) {
    const int gwarp = (int)((blockIdx.x * blockDim.x + threadIdx.x) >> 5);
    const int lane  = threadIdx.x & 31;

    // Blocked: warp covers rows [4*gwarp, 4*gwarp+4).
    const float* __restrict__ a0 = A + (size_t)gwarp * (ROWS_PER_WARP * 54);
    const float* __restrict__ b0 = B + (size_t)gwarp * (ROWS_PER_WARP * 54);

    float av0[ROWS_PER_WARP], bv0[ROWS_PER_WARP];
    float av1[ROWS_PER_WARP], bv1[ROWS_PER_WARP];

    const bool tail = (lane < 22);

    // 16 independent LDG.32, small constant offsets (i*216B) -> immediate form.
    #pragma unroll
    for (int i = 0; i < ROWS_PER_WARP; i++) {
        const int off = i * 54;
        av0[i] = a0[off + lane];
        bv0[i] = b0[off + lane];
        av1[i] = 0.0f; bv1[i] = 0.0f;
        if (tail) {
            av1[i] = a0[off + 32 + lane];
            bv1[i] = b0[off + 32 + lane];
        }
    }

    // Output: contiguous 1728B region for the 4 rows.
    uint4* __restrict__ o = (uint4*)(out + (size_t)gwarp * (ROWS_PER_WARP * 108));

    #pragma unroll
    for (int i = 0; i < ROWS_PER_WARP; i++) {
        unsigned ma0 = __ballot_sync(0xFFFFFFFFu, av0[i] > 0.5f);
        unsigned ma1 = __ballot_sync(0xFFFFFFFFu, av1[i] > 0.5f);
        unsigned mb0 = __ballot_sync(0xFFFFFFFFu, bv0[i] > 0.5f);
        unsigned mb1 = __ballot_sync(0xFFFFFFFFu, bv1[i] > 0.5f);

        const uint64_t a = (uint64_t)ma0 | ((uint64_t)(ma1 & 0x3FFFFFu) << 32);
        const uint64_t b = (uint64_t)mb0 | ((uint64_t)(mb1 & 0x3FFFFFu) << 32);

        const uint64_t lo = a * b;             // product bits [0:64)
        const uint64_t hi = __umul64hi(a, b);  // product bits [64:108)

        if (lane < 27) {
            unsigned nib = (lane < 16) ? (unsigned)(lo >> (lane * 4))
                                       : (unsigned)(hi >> ((lane - 16) * 4));
            uint4 v;
            v.x = ( nib        & 1u) * 0x3F800000u;
            v.y = ((nib >> 1)  & 1u) * 0x3F800000u;
            v.z = ((nib >> 2)  & 1u) * 0x3F800000u;
            v.w = ((nib >> 3)  & 1u) * 0x3F800000u;
            o[i * 27 + lane] = v;
        }
    }
}

// Generic fallback for unexpected batch sizes (1 row/warp, guarded).
__global__ void __launch_bounds__(256)
mul54x54_generic_kernel(const float* __restrict__ A,
                        const float* __restrict__ B,
                        float* __restrict__ out,
                        int batch) {
    const int row  = (int)((blockIdx.x * blockDim.x + threadIdx.x) >> 5);
    const int lane = threadIdx.x & 31;
    if (row >= batch) return;

    const float* __restrict__ a_row = A + (size_t)row * 54;
    const float* __restrict__ b_row = B + (size_t)row * 54;

    float av0 = a_row[lane], bv0 = b_row[lane];
    float av1 = 0.0f, bv1 = 0.0f;
    if (lane < 22) { av1 = a_row[32 + lane]; bv1 = b_row[32 + lane]; }

    unsigned ma0 = __ballot_sync(0xFFFFFFFFu, av0 > 0.5f);
    unsigned ma1 = __ballot_sync(0xFFFFFFFFu, av1 > 0.5f);
    unsigned mb0 = __ballot_sync(0xFFFFFFFFu, bv0 > 0.5f);
    unsigned mb1 = __ballot_sync(0xFFFFFFFFu, bv1 > 0.5f);

    const uint64_t a = (uint64_t)ma0 | ((uint64_t)(ma1 & 0x3FFFFFu) << 32);
    const uint64_t b = (uint64_t)mb0 | ((uint64_t)(mb1 & 0x3FFFFFu) << 32);
    const uint64_t lo = a * b;
    const uint64_t hi = __umul64hi(a, b);

    if (lane < 27) {
        unsigned nib = (lane < 16) ? (unsigned)(lo >> (lane * 4))
                                   : (unsigned)(hi >> ((lane - 16) * 4));
        uint4 v;
        v.x = ( nib        & 1u) * 0x3F800000u;
        v.y = ((nib >> 1)  & 1u) * 0x3F800000u;
        v.z = ((nib >> 2)  & 1u) * 0x3F800000u;
        v.w = ((nib >> 3)  & 1u) * 0x3F800000u;
        ((uint4*)(out + (size_t)row * 108))[lane] = v;
    }
}

extern "C" void kernel_launch(void* const* d_in, const int* in_sizes, int n_in,
                              void* d_out, int out_size) {
    const float* A = (const float*)d_in[0];
    const float* B = (const float*)d_in[1];
    float* out = (float*)d_out;

    const int batch = in_sizes[0] / 54;     // 8192 expected
    constexpr int NWARPS = 2048;            // 128 CTAs x 512 threads

    if (batch == NWARPS * ROWS_PER_WARP) {
        mul54x54_final_kernel<<<128, 512>>>(A, B, out);
    } else {
        const int blocks = (batch + 7) / 8; // 1 row/warp fallback
        mul54x54_generic_kernel<<<blocks, 256>>>(A, B, out, batch);
    }
}